// round 8
// baseline (speedup 1.0000x reference)
#include <cuda_runtime.h>
#include <cstdint>

#define N_SAMPLES 8192
#define M_DIM     64
#define A_DIM     2048
#define R_ROWS    16          // rows per CTA
#define TA        128         // atoms per shared tile
#define NTILES    (A_DIM / TA)
#define NTHREADS  256

// shared layout (bytes):
//   sh_w  : float2[M_DIM][TA]     = 64*128*8 = 65536
//   sh_ra : float2[R_ROWS][M_DIM] = 16*64*8  =  8192   (re, im)
//   sh_rb : float2[R_ROWS][M_DIM] = 16*64*8  =  8192   (im, -re)
//   sh_idx: int[R_ROWS]                       =    64
//   sh_val: float2[R_ROWS]                    =   128
#define SMEM_W_OFF    0
#define SMEM_RA_OFF   65536
#define SMEM_RB_OFF   (65536 + 8192)
#define SMEM_IDX_OFF  (65536 + 8192 + 8192)
#define SMEM_VAL_OFF  (SMEM_IDX_OFF + 64)
#define SMEM_BYTES    (SMEM_VAL_OFF + 128)

// ---- packed f32x2 helpers (sm_100+) ----
__device__ __forceinline__ unsigned long long pk2(float lo, float hi) {
    unsigned long long r;
    asm("mov.b64 %0, {%1, %2};" : "=l"(r) : "f"(lo), "f"(hi));
    return r;
}
__device__ __forceinline__ void upk2(unsigned long long v, float& lo, float& hi) {
    asm("mov.b64 {%0, %1}, %2;" : "=f"(lo), "=f"(hi) : "l"(v));
}
__device__ __forceinline__ unsigned long long fma2(unsigned long long a,
                                                   unsigned long long b,
                                                   unsigned long long c) {
    unsigned long long d;
    asm("fma.rn.f32x2 %0, %1, %2, %3;" : "=l"(d) : "l"(a), "l"(b), "l"(c));
    return d;
}

__global__ __launch_bounds__(NTHREADS, 2)
void mp_kernel(const float* __restrict__ xre, const float* __restrict__ xim,
               const float* __restrict__ Wre, const float* __restrict__ Wim,
               const int* __restrict__ kp, float* __restrict__ out,
               int out_size) {
    extern __shared__ char smem[];
    float2* sh_w   = reinterpret_cast<float2*>(smem + SMEM_W_OFF);    // [m*TA + a]
    float2* sh_ra  = reinterpret_cast<float2*>(smem + SMEM_RA_OFF);   // [row*M + m]
    float2* sh_rb  = reinterpret_cast<float2*>(smem + SMEM_RB_OFF);
    int*    sh_idx = reinterpret_cast<int*>(smem + SMEM_IDX_OFF);
    float2* sh_val = reinterpret_cast<float2*>(smem + SMEM_VAL_OFF);

    const int t    = threadIdx.x;
    const int warp = t >> 5;
    const int lane = t & 31;
    const int row0_g = blockIdx.x * R_ROWS;     // global first row of this CTA

    // ---- load residual = x0 for our 16 rows ----
    #pragma unroll
    for (int q = 0; q < (R_ROWS * M_DIM) / NTHREADS; q++) {
        int i = t + q * NTHREADS;               // 0..1023
        int row = i >> 6, m = i & 63;
        float re = xre[(row0_g + row) * M_DIM + m];
        float im = xim[(row0_g + row) * M_DIM + m];
        sh_ra[row * M_DIM + m] = make_float2(re, im);
        sh_rb[row * M_DIM + m] = make_float2(im, -re);
    }
    __syncthreads();

    const int k = kp[0];
    const int r0 = 2 * warp;                    // local rows owned by this warp
    const int r1 = 2 * warp + 1;

    for (int iter = 0; iter < k; iter++) {
        // per-lane running best for the two rows this warp owns
        float bm2[2]  = {-1.0f, -1.0f};
        int   bix[2]  = {0, 0};
        float bre[2]  = {0.0f, 0.0f};
        float bim[2]  = {0.0f, 0.0f};

        for (int tile = 0; tile < NTILES; tile++) {
            const int a0 = tile * TA;

            // ---- load W tile into shared as interleaved (re, im) float2 ----
            #pragma unroll
            for (int q = 0; q < (M_DIM * (TA / 2)) / NTHREADS; q++) {
                int i = t + q * NTHREADS;       // 0..4095
                int m = i >> 6, g = i & 63;     // g = atom pair within tile
                float2 re2 = reinterpret_cast<const float2*>(Wre + m * A_DIM + a0)[g];
                float2 im2 = reinterpret_cast<const float2*>(Wim + m * A_DIM + a0)[g];
                float4 v = make_float4(re2.x, im2.x, re2.y, im2.y);
                reinterpret_cast<float4*>(&sh_w[m * TA + 2 * g])[0] = v;
            }
            __syncthreads();

            // ---- accumulate scores: 2 rows x 4 atoms per thread ----
            unsigned long long acc0[4] = {0ull, 0ull, 0ull, 0ull};
            unsigned long long acc1[4] = {0ull, 0ull, 0ull, 0ull};
            const unsigned long long* raP0 =
                reinterpret_cast<const unsigned long long*>(sh_ra + r0 * M_DIM);
            const unsigned long long* rbP0 =
                reinterpret_cast<const unsigned long long*>(sh_rb + r0 * M_DIM);
            const unsigned long long* raP1 =
                reinterpret_cast<const unsigned long long*>(sh_ra + r1 * M_DIM);
            const unsigned long long* rbP1 =
                reinterpret_cast<const unsigned long long*>(sh_rb + r1 * M_DIM);

            #pragma unroll 8
            for (int m = 0; m < M_DIM; m++) {
                unsigned long long ra0 = raP0[m], rb0 = rbP0[m];
                unsigned long long ra1 = raP1[m], rb1 = rbP1[m];
                #pragma unroll
                for (int j = 0; j < 4; j++) {
                    float2 wv = sh_w[m * TA + lane + 32 * j];
                    unsigned long long wrr = pk2(wv.x, wv.x);
                    unsigned long long wii = pk2(wv.y, wv.y);
                    // s += r * conj(w):
                    //   s_re += r_re*w_re + r_im*w_im
                    //   s_im += r_im*w_re - r_re*w_im
                    acc0[j] = fma2(ra0, wrr, acc0[j]);
                    acc0[j] = fma2(rb0, wii, acc0[j]);
                    acc1[j] = fma2(ra1, wrr, acc1[j]);
                    acc1[j] = fma2(rb1, wii, acc1[j]);
                }
            }

            // fold tile results into running best (atom index strictly increases
            // across j and tiles for a fixed lane -> strict '>' keeps first max)
            #pragma unroll
            for (int j = 0; j < 4; j++) {
                int a = a0 + lane + 32 * j;
                float sre, sim;
                upk2(acc0[j], sre, sim);
                float m2 = fmaf(sre, sre, sim * sim);
                if (m2 > bm2[0]) { bm2[0] = m2; bix[0] = a; bre[0] = sre; bim[0] = sim; }
                upk2(acc1[j], sre, sim);
                m2 = fmaf(sre, sre, sim * sim);
                if (m2 > bm2[1]) { bm2[1] = m2; bix[1] = a; bre[1] = sre; bim[1] = sim; }
            }
            __syncthreads();   // tile buffer reuse
        }

        // ---- warp-level argmax reduction per row (tie -> smallest index) ----
        #pragma unroll
        for (int rr = 0; rr < 2; rr++) {
            float m2 = bm2[rr]; int bi = bix[rr];
            float vr = bre[rr]; float vi = bim[rr];
            #pragma unroll
            for (int o = 16; o > 0; o >>= 1) {
                float om2 = __shfl_xor_sync(0xffffffffu, m2, o);
                int   oi  = __shfl_xor_sync(0xffffffffu, bi, o);
                float ovr = __shfl_xor_sync(0xffffffffu, vr, o);
                float ovi = __shfl_xor_sync(0xffffffffu, vi, o);
                if (om2 > m2 || (om2 == m2 && oi < bi)) {
                    m2 = om2; bi = oi; vr = ovr; vi = ovi;
                }
            }
            if (lane == 0) {
                sh_idx[2 * warp + rr] = bi;
                sh_val[2 * warp + rr] = make_float2(vr, vi);
            }
        }
        __syncthreads();

        // ---- residual -= vals * W[:, idx] ----
        #pragma unroll
        for (int q = 0; q < (R_ROWS * M_DIM) / NTHREADS; q++) {
            int i = t + q * NTHREADS;
            int row = i >> 6, m = i & 63;
            int a = sh_idx[row];
            float2 v = sh_val[row];
            float wr = Wre[m * A_DIM + a];
            float wi = Wim[m * A_DIM + a];
            float2 r = sh_ra[row * M_DIM + m];
            float nre = r.x - (v.x * wr - v.y * wi);
            float nim = r.y - (v.x * wi + v.y * wr);
            sh_ra[row * M_DIM + m] = make_float2(nre, nim);
            sh_rb[row * M_DIM + m] = make_float2(nim, -nre);
        }
        __syncthreads();
    }

    // ---- write outputs ----
    // NM = number of complex elements per output array.
    // Layout is selected by out_size (number of float32 elements in d_out):
    //   out_size == 2*NM : complex->float32 cast kept REAL PARTS only:
    //                      [ re(residual) | re(x_hat) ]
    //   out_size >= 4*NM : PLANAR per output:
    //                      [ res_re | res_im | xhat_re | xhat_im ]
    const long long NM = (long long)N_SAMPLES * M_DIM;   // 524288 complex elems
    const bool planar4 = ((long long)out_size >= 4 * NM);
    const bool real2   = (!planar4 && (long long)out_size >= 2 * NM);

    #pragma unroll
    for (int q = 0; q < (R_ROWS * M_DIM) / NTHREADS; q++) {
        int i = t + q * NTHREADS;
        int row = i >> 6, m = i & 63;
        long long gi = (long long)(row0_g + row) * M_DIM + m;
        float2 r = sh_ra[row * M_DIM + m];
        float x0r = xre[gi], x0i = xim[gi];
        float xhr = x0r - r.x;     // x_hat = x0 - residual
        float xhi = x0i - r.y;
        if (planar4) {
            out[gi]          = r.x;     // res_re
            out[NM + gi]     = r.y;     // res_im
            out[2 * NM + gi] = xhr;     // xhat_re
            out[3 * NM + gi] = xhi;     // xhat_im
        } else if (real2) {
            out[gi]      = r.x;         // re(residual)
            out[NM + gi] = xhr;         // re(x_hat)
        } else if (gi < out_size) {
            out[gi] = r.x;              // fallback: at least residual real part
        }
    }
}

extern "C" void kernel_launch(void* const* d_in, const int* in_sizes, int n_in,
                              void* d_out, int out_size) {
    const float* xre = (const float*)d_in[0];
    const float* xim = (const float*)d_in[1];
    const float* Wre = (const float*)d_in[2];
    const float* Wim = (const float*)d_in[3];
    const int*   kp  = (const int*)d_in[4];

    cudaFuncSetAttribute(mp_kernel, cudaFuncAttributeMaxDynamicSharedMemorySize,
                         SMEM_BYTES);
    mp_kernel<<<N_SAMPLES / R_ROWS, NTHREADS, SMEM_BYTES>>>(
        xre, xim, Wre, Wim, kp, (float*)d_out, out_size);
}

// round 9
// speedup vs baseline: 1.1150x; 1.1150x over previous
#include <cuda_runtime.h>
#include <cstdint>

#define N_SAMPLES 8192
#define M_DIM     64
#define A_DIM     2048
#define R_ROWS    32          // rows per CTA (4 per warp)
#define TA        128         // atoms per shared tile
#define NTILES    (A_DIM / TA)
#define NTHREADS  256

// shared layout (bytes):
//   sh_w  : float4[M_DIM][TA/2]   = 64*64*16 = 65536   (re,im,re,im atom pairs)
//   sh_rr : float2[M_DIM][R_ROWS] = 64*32*8  = 16384   (r_re, r_re) duplicated
//   sh_ri : float2[M_DIM][R_ROWS] = 64*32*8  = 16384   (r_im, r_im) duplicated
//   sh_idx: int[R_ROWS]                      =   128
//   sh_val: float2[R_ROWS]                   =   256
#define SMEM_W_OFF    0
#define SMEM_RR_OFF   65536
#define SMEM_RI_OFF   (65536 + 16384)
#define SMEM_IDX_OFF  (65536 + 16384 + 16384)
#define SMEM_VAL_OFF  (SMEM_IDX_OFF + 128)
#define SMEM_BYTES    (SMEM_VAL_OFF + 256)

// ---- packed f32x2 helpers (sm_100+) ----
__device__ __forceinline__ void upk2(unsigned long long v, float& lo, float& hi) {
    asm("mov.b64 {%0, %1}, %2;" : "=f"(lo), "=f"(hi) : "l"(v));
}
__device__ __forceinline__ unsigned long long fma2(unsigned long long a,
                                                   unsigned long long b,
                                                   unsigned long long c) {
    unsigned long long d;
    asm("fma.rn.f32x2 %0, %1, %2, %3;" : "=l"(d) : "l"(a), "l"(b), "l"(c));
    return d;
}

__global__ __launch_bounds__(NTHREADS, 2)
void mp_kernel(const float* __restrict__ xre, const float* __restrict__ xim,
               const float* __restrict__ Wre, const float* __restrict__ Wim,
               const int* __restrict__ kp, float* __restrict__ out,
               int out_size) {
    extern __shared__ char smem[];
    float4*  sh_w4  = reinterpret_cast<float4*>(smem + SMEM_W_OFF);   // [m*(TA/2)+g]
    float2*  sh_rr  = reinterpret_cast<float2*>(smem + SMEM_RR_OFF);  // [m*R_ROWS+row]
    float2*  sh_ri  = reinterpret_cast<float2*>(smem + SMEM_RI_OFF);
    int*     sh_idx = reinterpret_cast<int*>(smem + SMEM_IDX_OFF);
    float2*  sh_val = reinterpret_cast<float2*>(smem + SMEM_VAL_OFF);

    const int t    = threadIdx.x;
    const int warp = t >> 5;
    const int lane = t & 31;
    const int row0_g = blockIdx.x * R_ROWS;

    // ---- init residual = x0, stored as duplicated (re,re)/(im,im) pairs ----
    // mapping: consecutive threads -> consecutive rows (conflict-free STS)
    #pragma unroll
    for (int q = 0; q < (R_ROWS * M_DIM) / NTHREADS; q++) {
        int i = t + q * NTHREADS;                // 0..2047
        int row = i & 31, m = i >> 5;
        float re = xre[(row0_g + row) * M_DIM + m];
        float im = xim[(row0_g + row) * M_DIM + m];
        sh_rr[m * R_ROWS + row] = make_float2(re, re);
        sh_ri[m * R_ROWS + row] = make_float2(im, im);
    }
    __syncthreads();

    const int k = kp[0];

    for (int iter = 0; iter < k; iter++) {
        // per-lane running best for the 4 rows this warp owns
        float bm2[4] = {-1.f, -1.f, -1.f, -1.f};
        int   bix[4] = {0, 0, 0, 0};
        float bre[4] = {0.f, 0.f, 0.f, 0.f};
        float bim[4] = {0.f, 0.f, 0.f, 0.f};

        for (int tile = 0; tile < NTILES; tile++) {
            const int a0 = tile * TA;

            // ---- load W tile into shared as (re,im,re,im) float4 atom pairs ----
            #pragma unroll
            for (int q = 0; q < (M_DIM * (TA / 2)) / NTHREADS; q++) {
                int i = t + q * NTHREADS;        // 0..4095
                int m = i >> 6, g = i & 63;      // g = atom pair
                float2 re2 = reinterpret_cast<const float2*>(Wre + m * A_DIM + a0)[g];
                float2 im2 = reinterpret_cast<const float2*>(Wim + m * A_DIM + a0)[g];
                sh_w4[m * (TA / 2) + g] = make_float4(re2.x, im2.x, re2.y, im2.y);
            }
            __syncthreads();

            // ---- accumulate: 4 rows x 4 atoms per thread ----
            // acc1[r][s] = sum_m (w_re*r_re, w_im*r_re)
            // acc2[r][s] = sum_m (w_re*r_im, w_im*r_im)
            unsigned long long acc1[16], acc2[16];
            #pragma unroll
            for (int z = 0; z < 16; z++) { acc1[z] = 0ull; acc2[z] = 0ull; }

            const ulonglong2* sw =
                reinterpret_cast<const ulonglong2*>(sh_w4);  // [m*64 + g]
            const ulonglong2* rrP = reinterpret_cast<const ulonglong2*>(
                sh_rr) + warp * 2;                           // rows 4w..4w+3 at [m*16 + 2w..]
            const ulonglong2* riP = reinterpret_cast<const ulonglong2*>(
                sh_ri) + warp * 2;

            #pragma unroll 2
            for (int m = 0; m < M_DIM; m++) {
                ulonglong2 rr01 = rrP[m * (R_ROWS / 2)];      // (rrow0, rrow1)
                ulonglong2 rr23 = rrP[m * (R_ROWS / 2) + 1];  // (rrow2, rrow3)
                ulonglong2 ri01 = riP[m * (R_ROWS / 2)];
                ulonglong2 ri23 = riP[m * (R_ROWS / 2) + 1];
                #pragma unroll
                for (int jj = 0; jj < 2; jj++) {
                    ulonglong2 w = sw[m * (TA / 2) + lane + 32 * jj];  // 2 atoms
                    int s0 = 2 * jj;
                    // row 0
                    acc1[0*4+s0]   = fma2(w.x, rr01.x, acc1[0*4+s0]);
                    acc1[0*4+s0+1] = fma2(w.y, rr01.x, acc1[0*4+s0+1]);
                    acc2[0*4+s0]   = fma2(w.x, ri01.x, acc2[0*4+s0]);
                    acc2[0*4+s0+1] = fma2(w.y, ri01.x, acc2[0*4+s0+1]);
                    // row 1
                    acc1[1*4+s0]   = fma2(w.x, rr01.y, acc1[1*4+s0]);
                    acc1[1*4+s0+1] = fma2(w.y, rr01.y, acc1[1*4+s0+1]);
                    acc2[1*4+s0]   = fma2(w.x, ri01.y, acc2[1*4+s0]);
                    acc2[1*4+s0+1] = fma2(w.y, ri01.y, acc2[1*4+s0+1]);
                    // row 2
                    acc1[2*4+s0]   = fma2(w.x, rr23.x, acc1[2*4+s0]);
                    acc1[2*4+s0+1] = fma2(w.y, rr23.x, acc1[2*4+s0+1]);
                    acc2[2*4+s0]   = fma2(w.x, ri23.x, acc2[2*4+s0]);
                    acc2[2*4+s0+1] = fma2(w.y, ri23.x, acc2[2*4+s0+1]);
                    // row 3
                    acc1[3*4+s0]   = fma2(w.x, rr23.y, acc1[3*4+s0]);
                    acc1[3*4+s0+1] = fma2(w.y, rr23.y, acc1[3*4+s0+1]);
                    acc2[3*4+s0]   = fma2(w.x, ri23.y, acc2[3*4+s0]);
                    acc2[3*4+s0+1] = fma2(w.y, ri23.y, acc2[3*4+s0+1]);
                }
            }

            // ---- epilogue: recombine + fold into running best ----
            // atom index for slot (jj,p): a = a0 + 64*jj + 2*lane + p
            // slot order (jj,p) = (0,0),(0,1),(1,0),(1,1) is strictly increasing
            // in a for fixed lane -> '>' keeps first occurrence.
            #pragma unroll
            for (int r = 0; r < 4; r++) {
                #pragma unroll
                for (int jj = 0; jj < 2; jj++) {
                    #pragma unroll
                    for (int p = 0; p < 2; p++) {
                        int s = r * 4 + 2 * jj + p;
                        int a = a0 + 64 * jj + 2 * lane + p;
                        float a1lo, a1hi, a2lo, a2hi;
                        upk2(acc1[s], a1lo, a1hi);
                        upk2(acc2[s], a2lo, a2hi);
                        float sre = a1lo + a2hi;       // w_re*r_re + w_im*r_im
                        float sim = a2lo - a1hi;       // w_re*r_im - w_im*r_re
                        float m2 = fmaf(sre, sre, sim * sim);
                        if (m2 > bm2[r]) {
                            bm2[r] = m2; bix[r] = a; bre[r] = sre; bim[r] = sim;
                        }
                    }
                }
            }
            __syncthreads();   // tile buffer reuse
        }

        // ---- warp-level argmax per row (tie -> smallest index) ----
        #pragma unroll
        for (int r = 0; r < 4; r++) {
            float m2 = bm2[r]; int bi = bix[r];
            float vr = bre[r]; float vi = bim[r];
            #pragma unroll
            for (int o = 16; o > 0; o >>= 1) {
                float om2 = __shfl_xor_sync(0xffffffffu, m2, o);
                int   oi  = __shfl_xor_sync(0xffffffffu, bi, o);
                float ovr = __shfl_xor_sync(0xffffffffu, vr, o);
                float ovi = __shfl_xor_sync(0xffffffffu, vi, o);
                if (om2 > m2 || (om2 == m2 && oi < bi)) {
                    m2 = om2; bi = oi; vr = ovr; vi = ovi;
                }
            }
            if (lane == 0) {
                sh_idx[4 * warp + r] = bi;
                sh_val[4 * warp + r] = make_float2(vr, vi);
            }
        }
        __syncthreads();

        // ---- residual -= vals * W[:, idx] (write duplicated pairs) ----
        // mapping: consecutive threads -> consecutive rows (conflict-free LDS/STS)
        #pragma unroll
        for (int q = 0; q < (R_ROWS * M_DIM) / NTHREADS; q++) {
            int i = t + q * NTHREADS;
            int row = i & 31, m = i >> 5;
            int a = sh_idx[row];
            float2 v = sh_val[row];
            float wr = Wre[m * A_DIM + a];
            float wi = Wim[m * A_DIM + a];
            float re = sh_rr[m * R_ROWS + row].x;
            float im = sh_ri[m * R_ROWS + row].x;
            float nre = re - (v.x * wr - v.y * wi);
            float nim = im - (v.x * wi + v.y * wr);
            sh_rr[m * R_ROWS + row] = make_float2(nre, nre);
            sh_ri[m * R_ROWS + row] = make_float2(nim, nim);
        }
        __syncthreads();
    }

    // ---- write outputs (layout selected by out_size, as validated) ----
    //   out_size >= 4*NM : planar [ res_re | res_im | xhat_re | xhat_im ]
    //   out_size >= 2*NM : real parts only [ re(residual) | re(x_hat) ]
    const long long NM = (long long)N_SAMPLES * M_DIM;
    const bool planar4 = ((long long)out_size >= 4 * NM);
    const bool real2   = (!planar4 && (long long)out_size >= 2 * NM);

    #pragma unroll
    for (int q = 0; q < (R_ROWS * M_DIM) / NTHREADS; q++) {
        int i = t + q * NTHREADS;
        int row = i >> 6, m = i & 63;            // coalesced global writes
        long long gi = (long long)(row0_g + row) * M_DIM + m;
        float rre = sh_rr[m * R_ROWS + row].x;
        float rim = sh_ri[m * R_ROWS + row].x;
        float x0r = xre[gi], x0i = xim[gi];
        float xhr = x0r - rre;
        float xhi = x0i - rim;
        if (planar4) {
            out[gi]          = rre;
            out[NM + gi]     = rim;
            out[2 * NM + gi] = xhr;
            out[3 * NM + gi] = xhi;
        } else if (real2) {
            out[gi]      = rre;
            out[NM + gi] = xhr;
        } else if (gi < out_size) {
            out[gi] = rre;
        }
    }
}

extern "C" void kernel_launch(void* const* d_in, const int* in_sizes, int n_in,
                              void* d_out, int out_size) {
    const float* xre = (const float*)d_in[0];
    const float* xim = (const float*)d_in[1];
    const float* Wre = (const float*)d_in[2];
    const float* Wim = (const float*)d_in[3];
    const int*   kp  = (const int*)d_in[4];

    cudaFuncSetAttribute(mp_kernel, cudaFuncAttributeMaxDynamicSharedMemorySize,
                         SMEM_BYTES);
    mp_kernel<<<N_SAMPLES / R_ROWS, NTHREADS, SMEM_BYTES>>>(
        xre, xim, Wre, Wim, kp, (float*)d_out, out_size);
}

// round 10
// speedup vs baseline: 3.5567x; 3.1900x over previous
#include <cuda_runtime.h>
#include <cstdint>

#define NS   8192
#define MD   64
#define AD   2048
#define RPC  8            // rows per CTA (main kernel)
#define NT   256

typedef unsigned long long u64;

// ---- device-global scratch (sanctioned: static __device__ arrays) ----
__device__ __align__(16) float2 d_Wint[MD * AD];   // 1 MB, (re,im) interleaved
__device__ __align__(16) float2 d_G[AD * AD];      // 32 MB Gram: G[a][b]=sum_m W[m,a]*conj(W[m,b])

// ---- packed f32x2 helpers ----
__device__ __forceinline__ u64 pk2(float lo, float hi) {
    u64 r; asm("mov.b64 %0,{%1,%2};" : "=l"(r) : "f"(lo), "f"(hi)); return r;
}
__device__ __forceinline__ void upk2(u64 v, float& lo, float& hi) {
    asm("mov.b64 {%0,%1},%2;" : "=f"(lo), "=f"(hi) : "l"(v));
}
__device__ __forceinline__ u64 fma2(u64 a, u64 b, u64 c) {
    u64 d; asm("fma.rn.f32x2 %0,%1,%2,%3;" : "=l"(d) : "l"(a), "l"(b), "l"(c)); return d;
}

// ============================================================
// Kernel 0: interleave W planes into float2
// ============================================================
__global__ void k_interleave(const float* __restrict__ Wre,
                             const float* __restrict__ Wim) {
    int i = blockIdx.x * blockDim.x + threadIdx.x;
    if (i < MD * AD) d_Wint[i] = make_float2(Wre[i], Wim[i]);
}

// ============================================================
// Kernel 1: Gram matrix G[a][b] = sum_m W[m,a] * conj(W[m,b])
// grid (64, 4): 32 a-rows x 512 b per CTA
// ============================================================
#define GA 32
__global__ __launch_bounds__(NT) void k_gram() {
    __shared__ float2 sh_ar[MD][GA];   // (a_re, a_re)
    __shared__ float2 sh_ai[MD][GA];   // (a_im, a_im)
    int t = threadIdx.x, warp = t >> 5, lane = t & 31;
    int a0 = blockIdx.x * GA, b0 = blockIdx.y * 512;

    for (int i = t; i < MD * GA; i += NT) {
        int m = i >> 5, a = i & 31;
        float2 w = d_Wint[m * AD + a0 + a];
        sh_ar[m][a] = make_float2(w.x, w.x);
        sh_ai[m][a] = make_float2(w.y, w.y);
    }
    __syncthreads();

    const u64* Wu = (const u64*)d_Wint;
    const ulonglong2* rr = (const ulonglong2*)sh_ar;  // [m*16 + pair]
    const ulonglong2* ri = (const ulonglong2*)sh_ai;

    for (int c = 0; c < 4; c++) {
        int bb = b0 + c * 128 + lane;
        u64 a1[4][4], a2[4][4];
        #pragma unroll
        for (int r = 0; r < 4; r++)
            #pragma unroll
            for (int j = 0; j < 4; j++) { a1[r][j] = 0ull; a2[r][j] = 0ull; }

        #pragma unroll 2
        for (int m = 0; m < MD; m++) {
            u64 wv[4];
            #pragma unroll
            for (int j = 0; j < 4; j++) wv[j] = Wu[m * AD + bb + 32 * j];
            ulonglong2 rA = rr[m * 16 + warp * 2], rB = rr[m * 16 + warp * 2 + 1];
            ulonglong2 iA = ri[m * 16 + warp * 2], iB = ri[m * 16 + warp * 2 + 1];
            u64 ar[4] = {rA.x, rA.y, rB.x, rB.y};
            u64 ai[4] = {iA.x, iA.y, iB.x, iB.y};
            #pragma unroll
            for (int r = 0; r < 4; r++)
                #pragma unroll
                for (int j = 0; j < 4; j++) {
                    a1[r][j] = fma2(wv[j], ar[r], a1[r][j]);
                    a2[r][j] = fma2(wv[j], ai[r], a2[r][j]);
                }
        }
        #pragma unroll
        for (int r = 0; r < 4; r++)
            #pragma unroll
            for (int j = 0; j < 4; j++) {
                float l1, h1, l2, h2;
                upk2(a1[r][j], l1, h1); upk2(a2[r][j], l2, h2);
                float gre = l1 + h2;          // a_re*w_re + a_im*w_im
                float gim = l2 - h1;          // a_im*w_re - a_re*w_im
                d_G[(size_t)(a0 + 4 * warp + r) * AD + (bb + 32 * j)] =
                    make_float2(gre, gim);
            }
    }
}

// ============================================================
// Kernel 2: main — phase1 full scoring + phase2 incremental MP
// smem: sh_s float2[8][2048]=131072 | sh_rr/sh_ri float2[64][8]=4096 ea
//       sh_red float4[8][8]=1024
// ============================================================
#define SM_S    0
#define SM_RR   131072
#define SM_RI   (131072 + 4096)
#define SM_RED  (131072 + 8192)
#define SM_MAIN (SM_RED + 1024)

__global__ __launch_bounds__(NT) void k_main(const float* __restrict__ xre,
                                             const float* __restrict__ xim,
                                             const int* __restrict__ kp,
                                             float* __restrict__ out,
                                             int out_size) {
    extern __shared__ char smem[];
    float2* sh_s   = (float2*)(smem + SM_S);     // [row*AD + atom]
    float2* sh_rr  = (float2*)(smem + SM_RR);    // [m*8 + row] (re,re)
    float2* sh_ri  = (float2*)(smem + SM_RI);    // [m*8 + row] (im,im)
    float4* sh_red = (float4*)(smem + SM_RED);   // [row*8 + warp]

    int t = threadIdx.x, warp = t >> 5, lane = t & 31;
    int row0 = blockIdx.x * RPC;

    // x -> duplicated pairs in smem
    for (int i = t; i < RPC * MD; i += NT) {
        int row = i >> 6, m = i & 63;
        float re = xre[(row0 + row) * MD + m];
        float im = xim[(row0 + row) * MD + m];
        sh_rr[m * RPC + row] = make_float2(re, re);
        sh_ri[m * RPC + row] = make_float2(im, im);
    }
    __syncthreads();

    const int k = kp[0];

    // ---------- phase 1: score all atoms once, 8 rows share W reads ----------
    float bm2[8], bre[8], bim[8]; int bix[8];
    #pragma unroll
    for (int r = 0; r < 8; r++) { bm2[r] = -1.f; bix[r] = 0; bre[r] = 0.f; bim[r] = 0.f; }

    const u64* Wu = (const u64*)d_Wint;
    const ulonglong2* rr2 = (const ulonglong2*)sh_rr;  // [m*4 + pair]
    const ulonglong2* ri2 = (const ulonglong2*)sh_ri;

    for (int c = 0; c < 8; c++) {
        const int A = c * 256 + warp * 32 + lane;
        u64 a1[8], a2[8];
        #pragma unroll
        for (int r = 0; r < 8; r++) { a1[r] = 0ull; a2[r] = 0ull; }

        #pragma unroll 4
        for (int m = 0; m < MD; m++) {
            u64 w = Wu[m * AD + A];
            ulonglong2 rA = rr2[m * 4 + 0], rB = rr2[m * 4 + 1];
            ulonglong2 rC = rr2[m * 4 + 2], rD = rr2[m * 4 + 3];
            ulonglong2 iA = ri2[m * 4 + 0], iB = ri2[m * 4 + 1];
            ulonglong2 iC = ri2[m * 4 + 2], iD = ri2[m * 4 + 3];
            a1[0] = fma2(w, rA.x, a1[0]);  a2[0] = fma2(w, iA.x, a2[0]);
            a1[1] = fma2(w, rA.y, a1[1]);  a2[1] = fma2(w, iA.y, a2[1]);
            a1[2] = fma2(w, rB.x, a1[2]);  a2[2] = fma2(w, iB.x, a2[2]);
            a1[3] = fma2(w, rB.y, a1[3]);  a2[3] = fma2(w, iB.y, a2[3]);
            a1[4] = fma2(w, rC.x, a1[4]);  a2[4] = fma2(w, iC.x, a2[4]);
            a1[5] = fma2(w, rC.y, a1[5]);  a2[5] = fma2(w, iC.y, a2[5]);
            a1[6] = fma2(w, rD.x, a1[6]);  a2[6] = fma2(w, iD.x, a2[6]);
            a1[7] = fma2(w, rD.y, a1[7]);  a2[7] = fma2(w, iD.y, a2[7]);
        }
        #pragma unroll
        for (int r = 0; r < 8; r++) {
            float l1, h1, l2, h2;
            upk2(a1[r], l1, h1); upk2(a2[r], l2, h2);
            float sre = l1 + h2;      // r_re*w_re + r_im*w_im
            float sim = l2 - h1;      // r_im*w_re - r_re*w_im
            sh_s[r * AD + A] = make_float2(sre, sim);
            float m2 = fmaf(sre, sre, sim * sim);
            if (m2 > bm2[r]) { bm2[r] = m2; bix[r] = A; bre[r] = sre; bim[r] = sim; }
        }
    }

    // per-warp argmax per row -> sh_red
    #pragma unroll
    for (int r = 0; r < 8; r++) {
        float m2 = bm2[r]; int ix = bix[r]; float vr = bre[r], vi = bim[r];
        #pragma unroll
        for (int o = 16; o > 0; o >>= 1) {
            float om  = __shfl_xor_sync(0xffffffffu, m2, o);
            int   oi  = __shfl_xor_sync(0xffffffffu, ix, o);
            float ovr = __shfl_xor_sync(0xffffffffu, vr, o);
            float ovi = __shfl_xor_sync(0xffffffffu, vi, o);
            if (om > m2 || (om == m2 && oi < ix)) { m2 = om; ix = oi; vr = ovr; vi = ovi; }
        }
        if (lane == 0) sh_red[r * 8 + warp] = make_float4(m2, __int_as_float(ix), vr, vi);
    }
    __syncthreads();

    // warp w owns row w from here on. Init residual (2 m per lane) in regs.
    const int m0 = lane, m1 = lane + 32;
    const long long gbase = (long long)(row0 + warp) * MD;
    const float x0r0 = xre[gbase + m0], x0i0 = xim[gbase + m0];
    const float x0r1 = xre[gbase + m1], x0i1 = xim[gbase + m1];
    float rr0 = x0r0, ri0 = x0i0, rr1 = x0r1, ri1 = x0i1;

    // combine 8 warp candidates for row `warp`
    float cm2 = -1.f; int cix = 0; float cvr = 0.f, cvi = 0.f;
    if (lane < 8) {
        float4 cd = sh_red[warp * 8 + lane];
        cm2 = cd.x; cix = __int_as_float(0), cix = __float_as_int(cd.y);
        cvr = cd.z; cvi = cd.w;
    }
    #pragma unroll
    for (int o = 4; o > 0; o >>= 1) {
        float om  = __shfl_xor_sync(0xffffffffu, cm2, o);
        int   oi  = __shfl_xor_sync(0xffffffffu, cix, o);
        float ovr = __shfl_xor_sync(0xffffffffu, cvr, o);
        float ovi = __shfl_xor_sync(0xffffffffu, cvi, o);
        if (om > cm2 || (om == cm2 && oi < cix)) { cm2 = om; cix = oi; cvr = ovr; cvi = ovi; }
    }
    cix = __shfl_sync(0xffffffffu, cix, 0);
    cvr = __shfl_sync(0xffffffffu, cvr, 0);
    cvi = __shfl_sync(0xffffffffu, cvi, 0);

    // apply pick 0
    if (k >= 1) {
        float2 w0 = d_Wint[m0 * AD + cix], w1 = d_Wint[m1 * AD + cix];
        rr0 -= cvr * w0.x - cvi * w0.y;  ri0 -= cvr * w0.y + cvi * w0.x;
        rr1 -= cvr * w1.x - cvi * w1.y;  ri1 -= cvr * w1.y + cvi * w1.x;
    }

    // ---------- phase 2: incremental sweeps, barrier-free per warp ----------
    ulonglong2* srow = (ulonglong2*)(sh_s + warp * AD);   // pair p = 2 atoms
    for (int it = 1; it < k; it++) {
        const float4* grow = (const float4*)(d_G + (size_t)cix * AD);
        const u64 c1 = pk2(-cvr, -cvr);
        const u64 c2 = pk2(cvi, -cvi);
        float nm2 = -1.f; int nix = 0; float nvr = 0.f, nvi = 0.f;

        #pragma unroll 4
        for (int j = 0; j < 32; j++) {
            int p = lane + 32 * j;
            float4 q = grow[p];                  // (g0re,g0im,g1re,g1im)
            ulonglong2 sp = srow[p];
            u64 g0  = pk2(q.x, q.y), g0s = pk2(q.y, q.x);
            u64 g1  = pk2(q.z, q.w), g1s = pk2(q.w, q.z);
            // s_new = s - v*g  =  fma2(g, (-vr,-vr), fma2(swap(g), (vi,-vi), s))
            u64 s0 = fma2(g0, c1, fma2(g0s, c2, sp.x));
            u64 s1 = fma2(g1, c1, fma2(g1s, c2, sp.y));
            srow[p] = make_ulonglong2(s0, s1);
            float r0, i0, r1, i1;
            upk2(s0, r0, i0); upk2(s1, r1, i1);
            float m2a = fmaf(r0, r0, i0 * i0);
            float m2b = fmaf(r1, r1, i1 * i1);
            if (m2a > nm2) { nm2 = m2a; nix = 2 * p;     nvr = r0; nvi = i0; }
            if (m2b > nm2) { nm2 = m2b; nix = 2 * p + 1; nvr = r1; nvi = i1; }
        }
        #pragma unroll
        for (int o = 16; o > 0; o >>= 1) {
            float om  = __shfl_xor_sync(0xffffffffu, nm2, o);
            int   oi  = __shfl_xor_sync(0xffffffffu, nix, o);
            float ovr = __shfl_xor_sync(0xffffffffu, nvr, o);
            float ovi = __shfl_xor_sync(0xffffffffu, nvi, o);
            if (om > nm2 || (om == nm2 && oi < nix)) { nm2 = om; nix = oi; nvr = ovr; nvi = ovi; }
        }
        cix = nix; cvr = nvr; cvi = nvi;

        float2 w0 = d_Wint[m0 * AD + cix], w1 = d_Wint[m1 * AD + cix];
        rr0 -= cvr * w0.x - cvi * w0.y;  ri0 -= cvr * w0.y + cvi * w0.x;
        rr1 -= cvr * w1.x - cvi * w1.y;  ri1 -= cvr * w1.y + cvi * w1.x;
    }

    // ---------- outputs (planar4 validated; real2 fallback) ----------
    const long long NM = (long long)NS * MD;
    if ((long long)out_size >= 4 * NM) {
        out[gbase + m0]          = rr0;
        out[NM + gbase + m0]     = ri0;
        out[2 * NM + gbase + m0] = x0r0 - rr0;
        out[3 * NM + gbase + m0] = x0i0 - ri0;
        out[gbase + m1]          = rr1;
        out[NM + gbase + m1]     = ri1;
        out[2 * NM + gbase + m1] = x0r1 - rr1;
        out[3 * NM + gbase + m1] = x0i1 - ri1;
    } else if ((long long)out_size >= 2 * NM) {
        out[gbase + m0]      = rr0;
        out[NM + gbase + m0] = x0r0 - rr0;
        out[gbase + m1]      = rr1;
        out[NM + gbase + m1] = x0r1 - rr1;
    }
}

extern "C" void kernel_launch(void* const* d_in, const int* in_sizes, int n_in,
                              void* d_out, int out_size) {
    const float* xre = (const float*)d_in[0];
    const float* xim = (const float*)d_in[1];
    const float* Wre = (const float*)d_in[2];
    const float* Wim = (const float*)d_in[3];
    const int*   kp  = (const int*)d_in[4];

    k_interleave<<<(MD * AD + 255) / 256, 256>>>(Wre, Wim);
    k_gram<<<dim3(AD / GA, 4), NT>>>();

    cudaFuncSetAttribute(k_main, cudaFuncAttributeMaxDynamicSharedMemorySize,
                         SM_MAIN);
    k_main<<<NS / RPC, NT, SM_MAIN>>>(xre, xim, kp, (float*)d_out, out_size);
}